// round 5
// baseline (speedup 1.0000x reference)
#include <cuda_runtime.h>
#include <math.h>

// Problem constants (fixed shapes from setup_inputs)
#define BB   2
#define DD   128
#define HH   128
#define WW   128
#define IMG_ELEMS (BB*DD*HH*WW*4)    // 16777216
#define VOX       (BB*DD*HH*WW)      // 4194304

// Effective per-axis weights, double-float pairs:
// E[p][c] = sum_j gauss_tap[j] * keys_weight[p-7+j][c]  (zero pad outside [0,128))
__device__ float g_Ehi[128 * 4];
__device__ float g_Elo[128 * 4];

// ---------------- double-float (two-float) arithmetic -----------------
struct df { float h, l; };

__device__ __forceinline__ df qts(float a, float b) {          // |a| >= |b|
    float s = a + b;
    return { s, b - (s - a) };
}
__device__ __forceinline__ df two_sum(float a, float b) {
    float s = a + b;
    float t = s - a;
    return { s, (a - (s - t)) + (b - t) };
}
__device__ __forceinline__ df two_prod(float a, float b) {
    float p = a * b;
    return { p, fmaf(a, b, -p) };
}
__device__ __forceinline__ df df_mul(df a, df b) {
    df p = two_prod(a.h, b.h);
    p.l = p.l + (a.h * b.l + a.l * b.h);
    return qts(p.h, p.l);
}
__device__ __forceinline__ df df_mul_f(df a, float b) {
    df p = two_prod(a.h, b);
    p.l = p.l + a.l * b;
    return qts(p.h, p.l);
}
__device__ __forceinline__ df df_add(df a, df b) {
    df s = two_sum(a.h, b.h);
    s.l = s.l + (a.l + b.l);
    return qts(s.h, s.l);
}
// -----------------------------------------------------------------------

// Cephes/Eigen-style vectorized expf (what XLA:CPU emits) — VALIDATED, do not touch.
__device__ float cephes_expf(float x) {
    const float LOG2EF = 1.44269504088896341f;
    const float C1 = 0.693359375f;
    const float C2 = -2.12194440e-4f;
    float m = floorf(fmaf(x, LOG2EF, 0.5f));
    float r = fmaf(m, -C1, x);
    r = fmaf(m, -C2, r);
    float r2 = __fmul_rn(r, r);
    float y = 1.9875691500E-4f;
    y = fmaf(y, r, 1.3981999507E-3f);
    y = fmaf(y, r, 8.3334519073E-3f);
    y = fmaf(y, r, 4.1665795894E-2f);
    y = fmaf(y, r, 1.6666665459E-1f);
    y = fmaf(y, r, 5.0000001201E-1f);
    y = fmaf(y, r2, r);
    y = __fadd_rn(y, 1.0f);
    return ldexpf(y, (int)m);
}

// fp32 Keys cubic weight with separate roundings per op — VALIDATED.
__device__ float keys_f32_strict(float x) {
    float t1 = __fmul_rn(1.5f, x);
    float t2 = __fsub_rn(t1, 2.5f);
    float t3 = __fmul_rn(t2, x);
    float t4 = __fmul_rn(t3, x);
    float out = __fadd_rn(t4, 1.0f);
    if (x >= 1.0f) {
        float u1 = __fmul_rn(-0.5f, x);
        float u2 = __fadd_rn(u1, 2.5f);
        float u3 = __fmul_rn(u2, x);
        float u4 = __fsub_rn(u3, 4.0f);
        float u5 = __fmul_rn(u4, x);
        out = __fadd_rn(u5, 2.0f);
    }
    if (x >= 2.0f) out = 0.0f;
    return out;
}

__global__ void precompute_E_kernel() {
    int p = threadIdx.x;
    if (p >= 128) return;

    float kf[16];
    float ksum = 0.0f;
    #pragma unroll
    for (int j = 0; j < 16; ++j) {
        float off = (float)(j - 7);
        float sq = __fmul_rn(off, off);
        float arg = -__fdiv_rn(sq, 12.5f);
        kf[j] = cephes_expf(arg);
        ksum = __fadd_rn(ksum, kf[j]);
    }
    double taps[16];
    #pragma unroll
    for (int j = 0; j < 16; ++j)
        taps[j] = (double)__fdiv_rn(kf[j], ksum);

    double E[4] = {0.0, 0.0, 0.0, 0.0};
    #pragma unroll
    for (int j = 0; j < 16; ++j) {
        int q = p - 7 + j;
        if (q < 0 || q >= 128) continue;
        float sf = __fsub_rn(__fmul_rn(__fadd_rn((float)q, 0.5f), 0.03125f), 0.5f);
        float wc[4];
        float ssum = 0.0f;
        #pragma unroll
        for (int c = 0; c < 4; ++c) {
            float x = fabsf(__fsub_rn(sf, (float)c));
            wc[c] = keys_f32_strict(x);
            ssum = __fadd_rn(ssum, wc[c]);
        }
        #pragma unroll
        for (int c = 0; c < 4; ++c) {
            double w = (double)__fdiv_rn(wc[c], ssum);
            E[c] += taps[j] * w;
        }
    }
    #pragma unroll
    for (int c = 0; c < 4; ++c) {
        float hi = (float)E[c];
        g_Ehi[p * 4 + c] = hi;
        g_Elo[p * 4 + c] = (float)(E[c] - (double)hi);
    }
}

__device__ __forceinline__ int clamp127(int v) {
    return min(max(v, 0), 127);
}

// Collapse one w-half of the trilinear stencil to a weighted float4 partial.
// half: 0 -> column clamp(i0w), weight (1-tw); 1 -> column clamp(i0w+1), weight tw.
__device__ __forceinline__ float4 gather_half(
    const float4* __restrict__ img4, long base, int half,
    float wd, float wh, float ww)
{
    float fld = floorf(wd), flh = floorf(wh), flw = floorf(ww);
    float td = wd - fld, th = wh - flh, tw = ww - flw;
    int i0d = (int)fld, i0h = (int)flh, i0w = (int)flw;
    int d0 = clamp127(i0d), d1 = clamp127(i0d + 1);
    int h0 = clamp127(i0h), h1 = clamp127(i0h + 1);
    int wc = clamp127(i0w + half);
    float wwgt = half ? tw : (1.0f - tw);

    const float4* r00 = &img4[base + ((long)d0 * 128 + h0) * 128 + wc];
    const float4* r01 = &img4[base + ((long)d0 * 128 + h1) * 128 + wc];
    const float4* r10 = &img4[base + ((long)d1 * 128 + h0) * 128 + wc];
    const float4* r11 = &img4[base + ((long)d1 * 128 + h1) * 128 + wc];
    float4 c00 = *r00, c01 = *r01, c10 = *r10, c11 = *r11;

    float omh = 1.0f - th, omd = 1.0f - td;
    float4 out;
    float a, bb;
    a = c00.x * omh + c01.x * th; bb = c10.x * omh + c11.x * th;
    out.x = (a * omd + bb * td) * wwgt;
    a = c00.y * omh + c01.y * th; bb = c10.y * omh + c11.y * th;
    out.y = (a * omd + bb * td) * wwgt;
    a = c00.z * omh + c01.z * th; bb = c10.z * omh + c11.z * th;
    out.z = (a * omd + bb * td) * wwgt;
    a = c00.w * omh + c01.w * th; bb = c10.w * omh + c11.w * th;
    out.w = (a * omd + bb * td) * wwgt;
    return out;
}

__global__ void __launch_bounds__(128) deform_kernel(
    const float* __restrict__ img,     // [B,128,128,128,4]
    const float* __restrict__ coarse,  // [B,4,4,4,3]
    const int*   __restrict__ lbl,     // [B,128,128,128]
    float*       __restrict__ out)     // [IMG_ELEMS] image then [VOX] label
{
    __shared__ float s_coarse[192];
    __shared__ df    s_prod[16];
    __shared__ df    s_U[12];

    int bid = blockIdx.x;
    int h = bid & 127;
    int d = (bid >> 7) & 127;
    int b = bid >> 14;
    int t = threadIdx.x;

    for (int i = t; i < 192; i += 128) s_coarse[i] = coarse[b * 192 + i];
    if (t < 16) {
        int cd = t >> 2, ch = t & 3;
        df Ed = { g_Ehi[d * 4 + cd], g_Elo[d * 4 + cd] };
        df Eh = { g_Ehi[h * 4 + ch], g_Elo[h * 4 + ch] };
        s_prod[t] = df_mul(Ed, Eh);
    }
    __syncthreads();

    if (t < 12) {
        int cw = t / 3, comp = t - cw * 3;
        df acc = { 0.f, 0.f };
        #pragma unroll
        for (int k = 0; k < 16; ++k)
            acc = df_add(acc, df_mul_f(s_prod[k], s_coarse[(k * 4 + cw) * 3 + comp]));
        s_U[t] = acc;
    }
    __syncthreads();

    // Lane-pair mapping: warp covers w in [wbase, wbase+32).
    // even lane (2p)   -> voxel w = wbase + p,       loads w-half 0
    // odd  lane (2p+1) -> voxel w = wbase + 16 + p,  loads w-half 1
    int lane = t & 31;
    int p    = lane >> 1;
    int half = lane & 1;
    int wbase = (t >> 5) * 32;
    int myw  = wbase + (half ? 16 + p : p);

    // flow for MY voxel (bit-identical df math to round 4)
    df Ew0 = { g_Ehi[myw * 4 + 0], g_Elo[myw * 4 + 0] };
    df Ew1 = { g_Ehi[myw * 4 + 1], g_Elo[myw * 4 + 1] };
    df Ew2 = { g_Ehi[myw * 4 + 2], g_Elo[myw * 4 + 2] };
    df Ew3 = { g_Ehi[myw * 4 + 3], g_Elo[myw * 4 + 3] };

    float flow[3];
    #pragma unroll
    for (int comp = 0; comp < 3; ++comp) {
        df acc =           df_mul(Ew0, s_U[0 * 3 + comp]);
        acc = df_add(acc,  df_mul(Ew1, s_U[1 * 3 + comp]));
        acc = df_add(acc,  df_mul(Ew2, s_U[2 * 3 + comp]));
        acc = df_add(acc,  df_mul(Ew3, s_U[3 * 3 + comp]));
        flow[comp] = acc.h + acc.l;
    }
    float wd = (float)d   + 35.0f * flow[0];
    float wh = (float)h   + 35.0f * flow[1];
    float ww = (float)myw + 35.0f * flow[2];

    // partner's warp coords (exact bit exchange)
    float pwd = __shfl_xor_sync(0xffffffffu, wd, 1);
    float pwh = __shfl_xor_sync(0xffffffffu, wh, 1);
    float pww = __shfl_xor_sync(0xffffffffu, ww, 1);

    const float4* __restrict__ img4 = reinterpret_cast<const float4*>(img);
    long base = (long)b * (128 * 128 * 128);

    // my w-half for my voxel, and my w-half for partner's voxel
    float4 pm = gather_half(img4, base, half, wd, wh, ww);
    float4 pp = gather_half(img4, base, half, pwd, pwh, pww);

    // exchange pp: I receive the partner's partial for MY voxel
    float4 recv;
    recv.x = __shfl_xor_sync(0xffffffffu, pp.x, 1);
    recv.y = __shfl_xor_sync(0xffffffffu, pp.y, 1);
    recv.z = __shfl_xor_sync(0xffffffffu, pp.z, 1);
    recv.w = __shfl_xor_sync(0xffffffffu, pp.w, 1);

    float4 r;
    r.x = pm.x + recv.x;
    r.y = pm.y + recv.y;
    r.z = pm.z + recv.z;
    r.w = pm.w + recv.w;

    long ovox = base + ((long)d * 128 + h) * 128 + myw;
    reinterpret_cast<float4*>(out)[ovox] = r;

    // nearest-neighbor label from MY flow (unchanged numerics)
    int nd = clamp127((int)rintf(wd));
    int nh = clamp127((int)rintf(wh));
    int nw = clamp127((int)rintf(ww));
    int lv = lbl[base + ((long)nd * 128 + nh) * 128 + nw];
    out[IMG_ELEMS + ovox] = (float)lv;
}

extern "C" void kernel_launch(void* const* d_in, const int* in_sizes, int n_in,
                              void* d_out, int out_size) {
    const float* img = nullptr;
    const float* coarse = nullptr;
    const int*   lbl = nullptr;
    for (int i = 0; i < n_in; ++i) {
        if      (in_sizes[i] == IMG_ELEMS) img    = (const float*)d_in[i];
        else if (in_sizes[i] == 384)       coarse = (const float*)d_in[i];
        else if (in_sizes[i] == VOX)       lbl    = (const int*)d_in[i];
    }
    float* out = (float*)d_out;

    precompute_E_kernel<<<1, 128>>>();
    deform_kernel<<<BB * DD * HH, 128>>>(img, coarse, lbl, out);
}

// round 6
// speedup vs baseline: 1.1815x; 1.1815x over previous
#include <cuda_runtime.h>
#include <math.h>

// Problem constants (fixed shapes from setup_inputs)
#define BB   2
#define DD   128
#define HH   128
#define WW   128
#define IMG_ELEMS (BB*DD*HH*WW*4)    // 16777216
#define VOX       (BB*DD*HH*WW)      // 4194304

__device__ float g_Ehi[128 * 4];
__device__ float g_Elo[128 * 4];

// ---------------- double-float (two-float) arithmetic -----------------
struct df { float h, l; };

__device__ __forceinline__ df qts(float a, float b) {
    float s = a + b;
    return { s, b - (s - a) };
}
__device__ __forceinline__ df two_sum(float a, float b) {
    float s = a + b;
    float t = s - a;
    return { s, (a - (s - t)) + (b - t) };
}
__device__ __forceinline__ df two_prod(float a, float b) {
    float p = a * b;
    return { p, fmaf(a, b, -p) };
}
__device__ __forceinline__ df df_mul(df a, df b) {
    df p = two_prod(a.h, b.h);
    p.l = p.l + (a.h * b.l + a.l * b.h);
    return qts(p.h, p.l);
}
__device__ __forceinline__ df df_mul_f(df a, float b) {
    df p = two_prod(a.h, b);
    p.l = p.l + a.l * b;
    return qts(p.h, p.l);
}
__device__ __forceinline__ df df_add(df a, df b) {
    df s = two_sum(a.h, b.h);
    s.l = s.l + (a.l + b.l);
    return qts(s.h, s.l);
}
// -----------------------------------------------------------------------

// Cephes/Eigen-style vectorized expf (XLA:CPU) — VALIDATED, do not touch.
__device__ float cephes_expf(float x) {
    const float LOG2EF = 1.44269504088896341f;
    const float C1 = 0.693359375f;
    const float C2 = -2.12194440e-4f;
    float m = floorf(fmaf(x, LOG2EF, 0.5f));
    float r = fmaf(m, -C1, x);
    r = fmaf(m, -C2, r);
    float r2 = __fmul_rn(r, r);
    float y = 1.9875691500E-4f;
    y = fmaf(y, r, 1.3981999507E-3f);
    y = fmaf(y, r, 8.3334519073E-3f);
    y = fmaf(y, r, 4.1665795894E-2f);
    y = fmaf(y, r, 1.6666665459E-1f);
    y = fmaf(y, r, 5.0000001201E-1f);
    y = fmaf(y, r2, r);
    y = __fadd_rn(y, 1.0f);
    return ldexpf(y, (int)m);
}

// fp32 Keys cubic weight with separate roundings per op — VALIDATED.
__device__ float keys_f32_strict(float x) {
    float t1 = __fmul_rn(1.5f, x);
    float t2 = __fsub_rn(t1, 2.5f);
    float t3 = __fmul_rn(t2, x);
    float t4 = __fmul_rn(t3, x);
    float out = __fadd_rn(t4, 1.0f);
    if (x >= 1.0f) {
        float u1 = __fmul_rn(-0.5f, x);
        float u2 = __fadd_rn(u1, 2.5f);
        float u3 = __fmul_rn(u2, x);
        float u4 = __fsub_rn(u3, 4.0f);
        float u5 = __fmul_rn(u4, x);
        out = __fadd_rn(u5, 2.0f);
    }
    if (x >= 2.0f) out = 0.0f;
    return out;
}

// One thread per (p, c); per-(p,c) accumulation order bit-identical to the
// validated round-4 version (ascending j, E += taps[j]*w).
__global__ void precompute_E_kernel() {
    int tid = threadIdx.x;
    if (tid >= 512) return;
    int p = tid >> 2, c = tid & 3;

    float kf[16];
    float ksum = 0.0f;
    #pragma unroll
    for (int j = 0; j < 16; ++j) {
        float off = (float)(j - 7);
        float sq = __fmul_rn(off, off);
        float arg = -__fdiv_rn(sq, 12.5f);
        kf[j] = cephes_expf(arg);
        ksum = __fadd_rn(ksum, kf[j]);
    }

    double E = 0.0;
    #pragma unroll
    for (int j = 0; j < 16; ++j) {
        int q = p - 7 + j;
        if (q < 0 || q >= 128) continue;
        float sf = __fsub_rn(__fmul_rn(__fadd_rn((float)q, 0.5f), 0.03125f), 0.5f);
        float wc[4];
        float ssum = 0.0f;
        #pragma unroll
        for (int cc = 0; cc < 4; ++cc) {
            float x = fabsf(__fsub_rn(sf, (float)cc));
            wc[cc] = keys_f32_strict(x);
            ssum = __fadd_rn(ssum, wc[cc]);
        }
        double tap = (double)__fdiv_rn(kf[j], ksum);
        double w   = (double)__fdiv_rn(wc[c], ssum);
        E += tap * w;
    }
    float hi = (float)E;
    g_Ehi[p * 4 + c] = hi;
    g_Elo[p * 4 + c] = (float)(E - (double)hi);
}

__device__ __forceinline__ int clamp127(int v) {
    return min(max(v, 0), 127);
}

// Collapse one w-half of the trilinear stencil to a weighted float4 partial.
__device__ __forceinline__ float4 gather_half(
    const float4* __restrict__ img4, long base, int half,
    float wd, float wh, float ww)
{
    float fld = floorf(wd), flh = floorf(wh), flw = floorf(ww);
    float td = wd - fld, th = wh - flh, tw = ww - flw;
    int i0d = (int)fld, i0h = (int)flh, i0w = (int)flw;
    int d0 = clamp127(i0d), d1 = clamp127(i0d + 1);
    int h0 = clamp127(i0h), h1 = clamp127(i0h + 1);
    int wc = clamp127(i0w + half);
    float wwgt = half ? tw : (1.0f - tw);

    float4 c00 = img4[base + ((long)d0 * 128 + h0) * 128 + wc];
    float4 c01 = img4[base + ((long)d0 * 128 + h1) * 128 + wc];
    float4 c10 = img4[base + ((long)d1 * 128 + h0) * 128 + wc];
    float4 c11 = img4[base + ((long)d1 * 128 + h1) * 128 + wc];

    float omh = 1.0f - th, omd = 1.0f - td;
    float4 out;
    float a, bb;
    a = c00.x * omh + c01.x * th; bb = c10.x * omh + c11.x * th;
    out.x = (a * omd + bb * td) * wwgt;
    a = c00.y * omh + c01.y * th; bb = c10.y * omh + c11.y * th;
    out.y = (a * omd + bb * td) * wwgt;
    a = c00.z * omh + c01.z * th; bb = c10.z * omh + c11.z * th;
    out.z = (a * omd + bb * td) * wwgt;
    a = c00.w * omh + c01.w * th; bb = c10.w * omh + c11.w * th;
    out.w = (a * omd + bb * td) * wwgt;
    return out;
}

__global__ void __launch_bounds__(128) deform_kernel(
    const float* __restrict__ img,     // [B,128,128,128,4]
    const float* __restrict__ coarse,  // [B,4,4,4,3]
    const int*   __restrict__ lbl,     // [B,128,128,128]
    float*       __restrict__ out)     // [IMG_ELEMS] image then [VOX] label
{
    __shared__ float s_coarse[192];
    __shared__ df    s_prod[16];
    __shared__ df    s_U[12];

    int bid = blockIdx.x;
    int h = bid & 127;
    int d = (bid >> 7) & 127;
    int b = bid >> 14;
    int t = threadIdx.x;

    for (int i = t; i < 192; i += 128) s_coarse[i] = coarse[b * 192 + i];
    if (t < 16) {
        int cd = t >> 2, ch = t & 3;
        df Ed = { g_Ehi[d * 4 + cd], g_Elo[d * 4 + cd] };
        df Eh = { g_Ehi[h * 4 + ch], g_Elo[h * 4 + ch] };
        s_prod[t] = df_mul(Ed, Eh);
    }
    __syncthreads();

    if (t < 12) {
        int cw = t / 3, comp = t - cw * 3;
        df acc = { 0.f, 0.f };
        #pragma unroll
        for (int k = 0; k < 16; ++k)
            acc = df_add(acc, df_mul_f(s_prod[k], s_coarse[(k * 4 + cw) * 3 + comp]));
        s_U[t] = acc;
    }
    __syncthreads();

    int lane  = t & 31;
    int p     = lane >> 1;
    int half  = lane & 1;
    int wbase = (t >> 5) * 32;
    int myw   = wbase + lane;          // voxel owned for flow/label (R4-identical)

    // flow for MY voxel — bit-identical df math to round 4
    df Ew0 = { g_Ehi[myw * 4 + 0], g_Elo[myw * 4 + 0] };
    df Ew1 = { g_Ehi[myw * 4 + 1], g_Elo[myw * 4 + 1] };
    df Ew2 = { g_Ehi[myw * 4 + 2], g_Elo[myw * 4 + 2] };
    df Ew3 = { g_Ehi[myw * 4 + 3], g_Elo[myw * 4 + 3] };

    float flow[3];
    #pragma unroll
    for (int comp = 0; comp < 3; ++comp) {
        df acc =           df_mul(Ew0, s_U[0 * 3 + comp]);
        acc = df_add(acc,  df_mul(Ew1, s_U[1 * 3 + comp]));
        acc = df_add(acc,  df_mul(Ew2, s_U[2 * 3 + comp]));
        acc = df_add(acc,  df_mul(Ew3, s_U[3 * 3 + comp]));
        flow[comp] = acc.h + acc.l;
    }
    float wd = (float)d   + 35.0f * flow[0];
    float wh = (float)h   + 35.0f * flow[1];
    float ww = (float)myw + 35.0f * flow[2];

    const unsigned FULL = 0xffffffffu;
    const float4* __restrict__ img4 = reinterpret_cast<const float4*>(img);
    long base = (long)b * (128 * 128 * 128);

    // ---- gather call A: voxel wbase+p (lane pair 2p/2p+1 take halves 0/1) ----
    float wdA = __shfl_sync(FULL, wd, p);
    float whA = __shfl_sync(FULL, wh, p);
    float wwA = __shfl_sync(FULL, ww, p);
    float4 pA = gather_half(img4, base, half, wdA, whA, wwA);

    // ---- gather call B: voxel wbase+16+p ----
    float wdB = __shfl_sync(FULL, wd, 16 + p);
    float whB = __shfl_sync(FULL, wh, 16 + p);
    float wwB = __shfl_sync(FULL, ww, 16 + p);
    float4 pB = gather_half(img4, base, half, wdB, whB, wwB);

    // combine halves within each lane pair
    pA.x += __shfl_xor_sync(FULL, pA.x, 1);
    pA.y += __shfl_xor_sync(FULL, pA.y, 1);
    pA.z += __shfl_xor_sync(FULL, pA.z, 1);
    pA.w += __shfl_xor_sync(FULL, pA.w, 1);
    pB.x += __shfl_xor_sync(FULL, pB.x, 1);
    pB.y += __shfl_xor_sync(FULL, pB.y, 1);
    pB.z += __shfl_xor_sync(FULL, pB.z, 1);
    pB.w += __shfl_xor_sync(FULL, pB.w, 1);

    // even lane writes voxel wbase+p, odd lane writes wbase+16+p -> exact 0..31 coverage
    int outw = half ? (wbase + 16 + p) : (wbase + p);
    float4 r = half ? pB : pA;
    long ovoxImg = base + ((long)d * 128 + h) * 128 + outw;
    reinterpret_cast<float4*>(out)[ovoxImg] = r;

    // nearest-neighbor label from MY flow (unchanged numerics)
    int nd = clamp127((int)rintf(wd));
    int nh = clamp127((int)rintf(wh));
    int nw = clamp127((int)rintf(ww));
    int lv = lbl[base + ((long)nd * 128 + nh) * 128 + nw];
    long ovox = base + ((long)d * 128 + h) * 128 + myw;
    out[IMG_ELEMS + ovox] = (float)lv;
}

extern "C" void kernel_launch(void* const* d_in, const int* in_sizes, int n_in,
                              void* d_out, int out_size) {
    const float* img = nullptr;
    const float* coarse = nullptr;
    const int*   lbl = nullptr;
    for (int i = 0; i < n_in; ++i) {
        if      (in_sizes[i] == IMG_ELEMS) img    = (const float*)d_in[i];
        else if (in_sizes[i] == 384)       coarse = (const float*)d_in[i];
        else if (in_sizes[i] == VOX)       lbl    = (const int*)d_in[i];
    }
    float* out = (float*)d_out;

    precompute_E_kernel<<<1, 512>>>();
    deform_kernel<<<BB * DD * HH, 128>>>(img, coarse, lbl, out);
}

// round 7
// speedup vs baseline: 1.2423x; 1.0515x over previous
#include <cuda_runtime.h>
#include <math.h>

// Problem constants (fixed shapes from setup_inputs)
#define BB   2
#define DD   128
#define HH   128
#define WW   128
#define IMG_ELEMS (BB*DD*HH*WW*4)    // 16777216
#define VOX       (BB*DD*HH*WW)      // 4194304

__device__ float g_Ehi[128 * 4];
__device__ float g_Elo[128 * 4];

// ---------------- double-float (two-float) arithmetic -----------------
struct df { float h, l; };

__device__ __forceinline__ df qts(float a, float b) {
    float s = a + b;
    return { s, b - (s - a) };
}
__device__ __forceinline__ df two_sum(float a, float b) {
    float s = a + b;
    float t = s - a;
    return { s, (a - (s - t)) + (b - t) };
}
__device__ __forceinline__ df two_prod(float a, float b) {
    float p = a * b;
    return { p, fmaf(a, b, -p) };
}
__device__ __forceinline__ df df_mul(df a, df b) {
    df p = two_prod(a.h, b.h);
    p.l = p.l + (a.h * b.l + a.l * b.h);
    return qts(p.h, p.l);
}
__device__ __forceinline__ df df_mul_f(df a, float b) {
    df p = two_prod(a.h, b);
    p.l = p.l + a.l * b;
    return qts(p.h, p.l);
}
__device__ __forceinline__ df df_add(df a, df b) {
    df s = two_sum(a.h, b.h);
    s.l = s.l + (a.l + b.l);
    return qts(s.h, s.l);
}
// -----------------------------------------------------------------------

// Cephes/Eigen-style vectorized expf (XLA:CPU) — VALIDATED, do not touch.
__device__ float cephes_expf(float x) {
    const float LOG2EF = 1.44269504088896341f;
    const float C1 = 0.693359375f;
    const float C2 = -2.12194440e-4f;
    float m = floorf(fmaf(x, LOG2EF, 0.5f));
    float r = fmaf(m, -C1, x);
    r = fmaf(m, -C2, r);
    float r2 = __fmul_rn(r, r);
    float y = 1.9875691500E-4f;
    y = fmaf(y, r, 1.3981999507E-3f);
    y = fmaf(y, r, 8.3334519073E-3f);
    y = fmaf(y, r, 4.1665795894E-2f);
    y = fmaf(y, r, 1.6666665459E-1f);
    y = fmaf(y, r, 5.0000001201E-1f);
    y = fmaf(y, r2, r);
    y = __fadd_rn(y, 1.0f);
    return ldexpf(y, (int)m);
}

// fp32 Keys cubic weight with separate roundings per op — VALIDATED.
__device__ float keys_f32_strict(float x) {
    float t1 = __fmul_rn(1.5f, x);
    float t2 = __fsub_rn(t1, 2.5f);
    float t3 = __fmul_rn(t2, x);
    float t4 = __fmul_rn(t3, x);
    float out = __fadd_rn(t4, 1.0f);
    if (x >= 1.0f) {
        float u1 = __fmul_rn(-0.5f, x);
        float u2 = __fadd_rn(u1, 2.5f);
        float u3 = __fmul_rn(u2, x);
        float u4 = __fsub_rn(u3, 4.0f);
        float u5 = __fmul_rn(u4, x);
        out = __fadd_rn(u5, 2.0f);
    }
    if (x >= 2.0f) out = 0.0f;
    return out;
}

// One thread per (p, c); accumulation order bit-identical to validated version.
__global__ void precompute_E_kernel() {
    int tid = threadIdx.x;
    if (tid >= 512) return;
    int p = tid >> 2, c = tid & 3;

    float kf[16];
    float ksum = 0.0f;
    #pragma unroll
    for (int j = 0; j < 16; ++j) {
        float off = (float)(j - 7);
        float sq = __fmul_rn(off, off);
        float arg = -__fdiv_rn(sq, 12.5f);
        kf[j] = cephes_expf(arg);
        ksum = __fadd_rn(ksum, kf[j]);
    }

    double E = 0.0;
    #pragma unroll
    for (int j = 0; j < 16; ++j) {
        int q = p - 7 + j;
        if (q < 0 || q >= 128) continue;
        float sf = __fsub_rn(__fmul_rn(__fadd_rn((float)q, 0.5f), 0.03125f), 0.5f);
        float wc[4];
        float ssum = 0.0f;
        #pragma unroll
        for (int cc = 0; cc < 4; ++cc) {
            float x = fabsf(__fsub_rn(sf, (float)cc));
            wc[cc] = keys_f32_strict(x);
            ssum = __fadd_rn(ssum, wc[cc]);
        }
        double tap = (double)__fdiv_rn(kf[j], ksum);
        double w   = (double)__fdiv_rn(wc[c], ssum);
        E += tap * w;
    }
    float hi = (float)E;
    g_Ehi[p * 4 + c] = hi;
    g_Elo[p * 4 + c] = (float)(E - (double)hi);
}

__device__ __forceinline__ int clamp127(int v) {
    return min(max(v, 0), 127);
}

// Collapse one w-half of the trilinear stencil to a weighted float4 partial.
__device__ __forceinline__ float4 gather_half(
    const float4* __restrict__ img4, long base, int half,
    float wd, float wh, float ww)
{
    float fld = floorf(wd), flh = floorf(wh), flw = floorf(ww);
    float td = wd - fld, th = wh - flh, tw = ww - flw;
    int i0d = (int)fld, i0h = (int)flh, i0w = (int)flw;
    int d0 = clamp127(i0d), d1 = clamp127(i0d + 1);
    int h0 = clamp127(i0h), h1 = clamp127(i0h + 1);
    int wc = clamp127(i0w + half);
    float wwgt = half ? tw : (1.0f - tw);

    float4 c00 = img4[base + ((long)d0 * 128 + h0) * 128 + wc];
    float4 c01 = img4[base + ((long)d0 * 128 + h1) * 128 + wc];
    float4 c10 = img4[base + ((long)d1 * 128 + h0) * 128 + wc];
    float4 c11 = img4[base + ((long)d1 * 128 + h1) * 128 + wc];

    float omh = 1.0f - th, omd = 1.0f - td;
    float4 out;
    float a, bb;
    a = c00.x * omh + c01.x * th; bb = c10.x * omh + c11.x * th;
    out.x = (a * omd + bb * td) * wwgt;
    a = c00.y * omh + c01.y * th; bb = c10.y * omh + c11.y * th;
    out.y = (a * omd + bb * td) * wwgt;
    a = c00.z * omh + c01.z * th; bb = c10.z * omh + c11.z * th;
    out.z = (a * omd + bb * td) * wwgt;
    a = c00.w * omh + c01.w * th; bb = c10.w * omh + c11.w * th;
    out.w = (a * omd + bb * td) * wwgt;
    return out;
}

__global__ void __launch_bounds__(128) deform_kernel(
    const float* __restrict__ img,     // [B,128,128,128,4]
    const float* __restrict__ coarse,  // [B,4,4,4,3]
    const int*   __restrict__ lbl,     // [B,128,128,128]
    float*       __restrict__ out)     // [IMG_ELEMS] image then [VOX] label
{
    __shared__ float  s_coarse[192];
    __shared__ df     s_prod[16];
    __shared__ df     s_U[12];
    __shared__ float4 s_flow[128];     // (wd, wh, ww, pad) per w

    int bid = blockIdx.x;
    int h = bid & 127;
    int d = (bid >> 7) & 127;
    int b = bid >> 14;
    int t = threadIdx.x;

    for (int i = t; i < 192; i += 128) s_coarse[i] = coarse[b * 192 + i];
    if (t < 16) {
        int cd = t >> 2, ch = t & 3;
        df Ed = { g_Ehi[d * 4 + cd], g_Elo[d * 4 + cd] };
        df Eh = { g_Ehi[h * 4 + ch], g_Elo[h * 4 + ch] };
        s_prod[t] = df_mul(Ed, Eh);
    }
    __syncthreads();

    if (t < 12) {
        int cw = t / 3, comp = t - cw * 3;
        df acc = { 0.f, 0.f };
        #pragma unroll
        for (int k = 0; k < 16; ++k)
            acc = df_add(acc, df_mul_f(s_prod[k], s_coarse[(k * 4 + cw) * 3 + comp]));
        s_U[t] = acc;
    }
    __syncthreads();

    // flow for w = t — bit-identical df math to rounds 4/6
    df Ew0 = { g_Ehi[t * 4 + 0], g_Elo[t * 4 + 0] };
    df Ew1 = { g_Ehi[t * 4 + 1], g_Elo[t * 4 + 1] };
    df Ew2 = { g_Ehi[t * 4 + 2], g_Elo[t * 4 + 2] };
    df Ew3 = { g_Ehi[t * 4 + 3], g_Elo[t * 4 + 3] };

    float flow[3];
    #pragma unroll
    for (int comp = 0; comp < 3; ++comp) {
        df acc =           df_mul(Ew0, s_U[0 * 3 + comp]);
        acc = df_add(acc,  df_mul(Ew1, s_U[1 * 3 + comp]));
        acc = df_add(acc,  df_mul(Ew2, s_U[2 * 3 + comp]));
        acc = df_add(acc,  df_mul(Ew3, s_U[3 * 3 + comp]));
        flow[comp] = acc.h + acc.l;
    }
    float wd = (float)d + 35.0f * flow[0];
    float wh = (float)h + 35.0f * flow[1];
    float ww = (float)t + 35.0f * flow[2];

    s_flow[t] = make_float4(wd, wh, ww, 0.0f);

    long base = (long)b * (128 * 128 * 128);

    // nearest-neighbor label for my own voxel (w = t) — unchanged numerics
    {
        int nd = clamp127((int)rintf(wd));
        int nh = clamp127((int)rintf(wh));
        int nw = clamp127((int)rintf(ww));
        int lv = lbl[base + ((long)nd * 128 + nh) * 128 + nw];
        long ovox = base + ((long)d * 128 + h) * 128 + t;
        out[IMG_ELEMS + ovox] = (float)lv;
    }

    __syncwarp();   // s_flow visible within warp (targets are warp-local)

    int lane  = t & 31;
    int p     = lane >> 1;
    int half  = lane & 1;
    int wbase = (t >> 5) * 32;
    int vA    = wbase + p;
    int vB    = wbase + 16 + p;

    const float4* __restrict__ img4 = reinterpret_cast<const float4*>(img);

    float4 fA = s_flow[vA];
    float4 fB = s_flow[vB];
    float4 pA = gather_half(img4, base, half, fA.x, fA.y, fA.z);
    float4 pB = gather_half(img4, base, half, fB.x, fB.y, fB.z);

    // Single float4 cross-exchange: even lane finishes vA, odd lane finishes vB.
    const unsigned FULL = 0xffffffffu;
    float4 send = half ? pA : pB;   // the partial my partner needs
    float4 recv;
    recv.x = __shfl_xor_sync(FULL, send.x, 1);
    recv.y = __shfl_xor_sync(FULL, send.y, 1);
    recv.z = __shfl_xor_sync(FULL, send.z, 1);
    recv.w = __shfl_xor_sync(FULL, send.w, 1);

    float4 mine = half ? pB : pA;
    float4 r;
    r.x = mine.x + recv.x;
    r.y = mine.y + recv.y;
    r.z = mine.z + recv.z;
    r.w = mine.w + recv.w;

    int outw = half ? vB : vA;
    long ovoxImg = base + ((long)d * 128 + h) * 128 + outw;
    reinterpret_cast<float4*>(out)[ovoxImg] = r;
}

extern "C" void kernel_launch(void* const* d_in, const int* in_sizes, int n_in,
                              void* d_out, int out_size) {
    const float* img = nullptr;
    const float* coarse = nullptr;
    const int*   lbl = nullptr;
    for (int i = 0; i < n_in; ++i) {
        if      (in_sizes[i] == IMG_ELEMS) img    = (const float*)d_in[i];
        else if (in_sizes[i] == 384)       coarse = (const float*)d_in[i];
        else if (in_sizes[i] == VOX)       lbl    = (const int*)d_in[i];
    }
    float* out = (float*)d_out;

    precompute_E_kernel<<<1, 512>>>();
    deform_kernel<<<BB * DD * HH, 128>>>(img, coarse, lbl, out);
}